// round 11
// baseline (speedup 1.0000x reference)
#include <cuda_runtime.h>
#include <cuda_bf16.h>
#include <cstdint>

// Causal attention B=16, N=2048, D=256 fp32, mma.sync bf16 3-term split.
// R9: unified 8 warps; PV(kt-1) MMAs fused into the S(kt) ks-loop so the
// tensor pipe only drains during the epilogue. V is single-buffered and
// streamed in 16-row quarters (quarter q refilled with V(kt) right after
// PV(kt-1) finishes reading it at ks=4q+3). K(kt+1)+pm issued at q=3.
// No mbarriers; 5 __syncthreads per tile. P ping-pong 2x16KB.

#define NSEQ  2048
#define DH    256
#define BATCH 16
#define BQ    64
#define BK    64
#define NELEM (BATCH*NSEQ*DH)

__device__ __nv_bfloat16 g_qhi[NELEM];
__device__ __nv_bfloat16 g_qlo[NELEM];
__device__ __nv_bfloat16 g_khi[NELEM];
__device__ __nv_bfloat16 g_klo[NELEM];
__device__ __nv_bfloat16 g_vhi[NELEM];
__device__ __nv_bfloat16 g_vlo[NELEM];

// ---- smem byte offsets ----
#define O_PM   64       // pm[2][64] floats
#define O_LR   576      // 128 floats row sums
#define O_QHI  2048
#define O_QLO  34816
#define O_KHI  67584
#define O_KLO  100352
#define O_VHI  133120
#define O_VLO  165888
#define O_P0   198656   // P buf: hi +0 (8KB), lo +8192; buf stride 16384
#define SMEM_TOTAL 231424

__device__ __forceinline__ uint32_t smem_u32(const void* p){
    uint32_t a; asm("{ .reg .u64 t; cvta.to.shared.u64 t, %1; cvt.u32.u64 %0, t; }":"=r"(a):"l"(p)); return a;
}
__device__ __forceinline__ void ldsm4(uint32_t a, uint32_t r[4]){
    asm volatile("ldmatrix.sync.aligned.m8n8.x4.shared.b16 {%0,%1,%2,%3},[%4];"
                 :"=r"(r[0]),"=r"(r[1]),"=r"(r[2]),"=r"(r[3]):"r"(a));
}
__device__ __forceinline__ void ldsm4t(uint32_t a, uint32_t r[4]){
    asm volatile("ldmatrix.sync.aligned.m8n8.x4.trans.shared.b16 {%0,%1,%2,%3},[%4];"
                 :"=r"(r[0]),"=r"(r[1]),"=r"(r[2]),"=r"(r[3]):"r"(a));
}
__device__ __forceinline__ void mma16816(float c[4], const uint32_t a[4], uint32_t b0, uint32_t b1){
    asm volatile("mma.sync.aligned.m16n8k16.row.col.f32.bf16.bf16.f32 "
                 "{%0,%1,%2,%3},{%4,%5,%6,%7},{%8,%9},{%0,%1,%2,%3};"
                 :"+f"(c[0]),"+f"(c[1]),"+f"(c[2]),"+f"(c[3])
                 :"r"(a[0]),"r"(a[1]),"r"(a[2]),"r"(a[3]),"r"(b0),"r"(b1));
}
__device__ __forceinline__ void cpa16(uint32_t dst, const void* src){
    asm volatile("cp.async.cg.shared.global [%0],[%1],16;"::"r"(dst),"l"(src):"memory");
}
#define CP_COMMIT() asm volatile("cp.async.commit_group;":::"memory")
#define CP_WAIT0()  asm volatile("cp.async.wait_group 0;":::"memory")

__device__ __forceinline__ uint32_t pack2(float a, float b){
    __nv_bfloat162 h; h.x=__float2bfloat16(a); h.y=__float2bfloat16(b);
    return *reinterpret_cast<uint32_t*>(&h);
}
__device__ __forceinline__ uint32_t pack_hi2(float a, float b, float& ra, float& rb){
    __nv_bfloat16 ha=__float2bfloat16(a), hb=__float2bfloat16(b);
    ra = a - __bfloat162float(ha); rb = b - __bfloat162float(hb);
    __nv_bfloat162 h; h.x=ha; h.y=hb;
    return *reinterpret_cast<uint32_t*>(&h);
}

// ---- pass 1: fp32 -> bf16 hi/lo ----
__global__ void cvt_kernel(const float* __restrict__ Q, const float* __restrict__ K,
                           const float* __restrict__ V)
{
    int i = blockIdx.x*blockDim.x + threadIdx.x;
    float4 q = ((const float4*)Q)[i];
    q.x*=0.0625f; q.y*=0.0625f; q.z*=0.0625f; q.w*=0.0625f;
    float l0,l1,l2,l3;
    uint32_t h01,h23;
    h01 = pack_hi2(q.x,q.y,l0,l1); h23 = pack_hi2(q.z,q.w,l2,l3);
    ((uint32_t*)g_qhi)[2*i]=h01; ((uint32_t*)g_qhi)[2*i+1]=h23;
    ((uint32_t*)g_qlo)[2*i]=pack2(l0,l1); ((uint32_t*)g_qlo)[2*i+1]=pack2(l2,l3);
    float4 k = ((const float4*)K)[i];
    h01 = pack_hi2(k.x,k.y,l0,l1); h23 = pack_hi2(k.z,k.w,l2,l3);
    ((uint32_t*)g_khi)[2*i]=h01; ((uint32_t*)g_khi)[2*i+1]=h23;
    ((uint32_t*)g_klo)[2*i]=pack2(l0,l1); ((uint32_t*)g_klo)[2*i+1]=pack2(l2,l3);
    float4 v = ((const float4*)V)[i];
    h01 = pack_hi2(v.x,v.y,l0,l1); h23 = pack_hi2(v.z,v.w,l2,l3);
    ((uint32_t*)g_vhi)[2*i]=h01; ((uint32_t*)g_vhi)[2*i+1]=h23;
    ((uint32_t*)g_vlo)[2*i]=pack2(l0,l1); ((uint32_t*)g_vlo)[2*i+1]=pack2(l2,l3);
}

// cp.async a full 64x256 bf16 tile with 256 threads (8 chunks of 16B each)
__device__ __forceinline__ void load_tile256(uint32_t smb, uint32_t off,
                                             const __nv_bfloat16* gsrc, int tid)
{
    const char* gs = (const char*)gsrc;
    #pragma unroll
    for (int it=0; it<8; ++it){
        int cid = tid + it*256;
        int row = cid >> 5, c = cid & 31;
        uint32_t dst = smb + off + row*512 + (((uint32_t)(c ^ (row&7)))<<4);
        cpa16(dst, gs + row*512 + c*16);
    }
}
// cp.async one 16-row quarter (16x256 bf16) with 256 threads (2 chunks each)
__device__ __forceinline__ void load_vq(uint32_t smb, uint32_t off,
                                        const __nv_bfloat16* gq, int tid, int q)
{
    const char* gs = (const char*)gq;
    #pragma unroll
    for (int it=0; it<2; ++it){
        int cid = tid + it*256;
        int r16 = cid >> 5, c = cid & 31;
        uint32_t dst = smb + off + (q*16 + r16)*512 + (((uint32_t)(c ^ (r16&7)))<<4);
        cpa16(dst, gs + r16*512 + c*16);
    }
}

__global__ __launch_bounds__(256,1)
void fa_fused_kernel(const int* __restrict__ PMg, float* __restrict__ Og)
{
    extern __shared__ char sm[];
    const uint32_t smb = smem_u32(sm);
    const int tid=threadIdx.x, lane=tid&31, wid=tid>>5;
    const int rb = wid & 3, ch = wid >> 2;     // S cols ch*32 / O cols ch*128
    const int qt = (int)gridDim.x-1-(int)blockIdx.x;
    const int b  = blockIdx.y;
    const int qbase = qt*BQ;
    const size_t base = (size_t)b*NSEQ*DH;

    // ---- prologue: Q + K(0) + pm(0) ----
    load_tile256(smb, O_QHI, g_qhi + base + (size_t)qbase*DH, tid);
    load_tile256(smb, O_QLO, g_qlo + base + (size_t)qbase*DH, tid);
    load_tile256(smb, O_KHI, g_khi + base, tid);
    load_tile256(smb, O_KLO, g_klo + base, tid);
    CP_COMMIT();
    if (tid < BK)
        ((float*)(sm+O_PM))[tid] = PMg[(size_t)b*NSEQ + tid] ? 1.f : 0.f;

    // ---- per-lane ldmatrix geometry (R4-verified) ----
    const int rowA = rb*16 + (lane & 15);
    const int ahl  = lane >> 4;
    const int rxa  = rowA & 7;
    const uint32_t aQhi = smb + O_QHI + rowA*512;
    const uint32_t aQlo = smb + O_QLO + rowA*512;

    const int rowB = (lane & 7) + ((lane >> 4) << 3);
    const int bhl  = (lane >> 3) & 1;
    const int rxb  = rowB & 7;
    const uint32_t bKhi = smb + O_KHI + (ch*32 + rowB)*512;
    const uint32_t bKlo = smb + O_KLO + (ch*32 + rowB)*512;

    const int rowV = (lane & 7) + (((lane >> 3) & 1) << 3);
    const int vhl  = lane >> 4;
    const int rxv  = rowV & 7;
    const uint32_t bVhi = smb + O_VHI + rowV*512;
    const uint32_t bVlo = smb + O_VLO + rowV*512;

    float o[16][4];
    #pragma unroll
    for (int n=0;n<16;++n){ o[n][0]=0.f;o[n][1]=0.f;o[n][2]=0.f;o[n][3]=0.f; }
    float lsum0=0.f, lsum1=0.f;

    for (int kt=0; kt<=qt; ++kt){
        const int kbase = kt*BK;
        const int bp = kt & 1;
        const bool dopv = (kt > 0);

        CP_WAIT0();            // K(kt) + V(kt-1) quarters landed
        __syncthreads();       // visible CTA-wide; P(kt-1) stores visible

        const uint32_t aPhi = smb + O_P0 + (bp^1)*16384 + rowA*128;

        float sacc[4][4];
        #pragma unroll
        for (int j=0;j<4;++j){ sacc[j][0]=0.f;sacc[j][1]=0.f;sacc[j][2]=0.f;sacc[j][3]=0.f; }

        uint32_t pa_hi[4], pa_lo[4];

        #pragma unroll
        for (int q=0; q<4; ++q){
            if (dopv){
                uint32_t swp = (uint32_t)((q*2 + ahl) ^ rxa) << 4;
                ldsm4(aPhi + swp, pa_hi);
                ldsm4(aPhi + 8192 + swp, pa_lo);
            }
            #pragma unroll
            for (int ks4=0; ks4<4; ++ks4){
                const int ks = q*4 + ks4;
                // ---- S(kt) part: 12 MMAs ----
                uint32_t a_hi[4], a_lo[4];
                uint32_t swa = (uint32_t)((ks*2 + ahl) ^ rxa) << 4;
                ldsm4(aQhi + swa, a_hi);
                ldsm4(aQlo + swa, a_lo);
                uint32_t swb = (uint32_t)((ks*2 + bhl) ^ rxb) << 4;
                #pragma unroll
                for (int jp=0; jp<2; ++jp){
                    uint32_t bh[4], bl[4];
                    uint32_t rofs = (uint32_t)(jp*8192);
                    ldsm4(bKhi + rofs + swb, bh);
                    ldsm4(bKlo + rofs + swb, bl);
                    mma16816(sacc[2*jp],   a_hi, bh[0], bh[1]);
                    mma16816(sacc[2*jp+1], a_hi, bh[2], bh[3]);
                    mma16816(sacc[2*jp],   a_lo, bh[0], bh[1]);
                    mma16816(sacc[2*jp+1], a_lo, bh[2], bh[3]);
                    mma16816(sacc[2*jp],   a_hi, bl[0], bl[1]);
                    mma16816(sacc[2*jp+1], a_hi, bl[2], bl[3]);
                }
                // ---- PV(kt-1) part: 12 MMAs (V quarter q) ----
                if (dopv){
                    uint32_t vrow = (uint32_t)(q*8192);
                    #pragma unroll
                    for (int pp=0; pp<2; ++pp){
                        const int ncp = 2*ks4 + pp;
                        uint32_t vh[4], vl[4];
                        uint32_t sw = (uint32_t)(((ch*16 + ncp*2 + vhl) ^ rxv) << 4);
                        ldsm4t(bVhi + vrow + sw, vh);
                        ldsm4t(bVlo + vrow + sw, vl);
                        mma16816(o[2*ncp],   pa_hi, vh[0], vh[1]);
                        mma16816(o[2*ncp+1], pa_hi, vh[2], vh[3]);
                        mma16816(o[2*ncp],   pa_lo, vh[0], vh[1]);
                        mma16816(o[2*ncp+1], pa_lo, vh[2], vh[3]);
                        mma16816(o[2*ncp],   pa_hi, vl[0], vl[1]);
                        mma16816(o[2*ncp+1], pa_hi, vl[2], vl[3]);
                    }
                }
            }
            // ---- quarter boundary: refill V quarter q with V(kt) ----
            __syncthreads();   // all warps done reading V(kt-1) quarter q & (q==3) K(kt)
            load_vq(smb, O_VHI, g_vhi + base + (size_t)(kbase + q*16)*DH, tid, q);
            load_vq(smb, O_VLO, g_vlo + base + (size_t)(kbase + q*16)*DH, tid, q);
            if (q == 3 && kt < qt){
                const size_t nk = base + (size_t)(kbase+BK)*DH;
                load_tile256(smb, O_KHI, g_khi + nk, tid);
                load_tile256(smb, O_KLO, g_klo + nk, tid);
                if (tid < BK)
                    ((float*)(sm + O_PM + ((kt+1)&1)*256))[tid] =
                        PMg[(size_t)b*NSEQ + kbase + BK + tid] ? 1.f : 0.f;
            }
            CP_COMMIT();
        }

        // ---- epilogue: P(kt) = exp(S)*pad*(causal on diag) -> buffer bp ----
        const float* pmv = (const float*)(sm + O_PM + bp*256);
        const bool diag = (kt == qt);
        const int r0g = qbase + rb*16 + (lane>>2);
        const int rloc = rb*16 + (lane>>2);
        float rs0=0.f, rs1=0.f;
        char* pb = sm + O_P0 + bp*16384;
        #pragma unroll
        for (int j=0;j<4;++j){
            int c0 = ch*32 + j*8 + (lane&3)*2;
            float m0 = pmv[c0], m1 = pmv[c0+1];
            int gc0 = kbase + c0;
            float v0 = __expf(sacc[j][0]) * m0;
            float v1 = __expf(sacc[j][1]) * m1;
            float v2 = __expf(sacc[j][2]) * m0;
            float v3 = __expf(sacc[j][3]) * m1;
            if (diag){
                if (gc0   > r0g)   v0 = 0.f;
                if (gc0+1 > r0g)   v1 = 0.f;
                if (gc0   > r0g+8) v2 = 0.f;
                if (gc0+1 > r0g+8) v3 = 0.f;
            }
            rs0 += v0 + v1;  rs1 += v2 + v3;
            float l0,l1;
            uint32_t hA = pack_hi2(v0,v1,l0,l1);
            uint32_t lA = pack2(l0,l1);
            uint32_t hB = pack_hi2(v2,v3,l0,l1);
            uint32_t lB = pack2(l0,l1);
            int chunk = ch*4 + j;
            uint32_t sw  = (uint32_t)((chunk ^ (rloc&7))<<4) + (lane&3)*4;
            uint32_t o0 = rloc*128 + sw;
            uint32_t o2 = (rloc+8)*128 + sw;
            *(uint32_t*)(pb + o0)        = hA;
            *(uint32_t*)(pb + 8192 + o0) = lA;
            *(uint32_t*)(pb + o2)        = hB;
            *(uint32_t*)(pb + 8192 + o2) = lB;
        }
        rs0 += __shfl_xor_sync(0xffffffffu, rs0, 1);
        rs0 += __shfl_xor_sync(0xffffffffu, rs0, 2);
        rs1 += __shfl_xor_sync(0xffffffffu, rs1, 1);
        rs1 += __shfl_xor_sync(0xffffffffu, rs1, 2);
        lsum0 += rs0;  lsum1 += rs1;
    }

    // ---- trailing PV(qt) ----
    CP_WAIT0();            // V(qt) quarters landed
    __syncthreads();       // P(qt) stores visible
    {
        const uint32_t aPhi = smb + O_P0 + (qt&1)*16384 + rowA*128;
        for (int kks=0; kks<4; ++kks){
            uint32_t pa_hi[4], pa_lo[4];
            uint32_t swp = (uint32_t)((kks*2 + ahl) ^ rxa) << 4;
            ldsm4(aPhi + swp, pa_hi);
            ldsm4(aPhi + 8192 + swp, pa_lo);
            uint32_t vrow = (uint32_t)(kks*8192);
            #pragma unroll
            for (int ncp=0; ncp<8; ++ncp){
                uint32_t vh[4], vl[4];
                uint32_t sw = (uint32_t)(((ch*16 + ncp*2 + vhl) ^ rxv) << 4);
                ldsm4t(bVhi + vrow + sw, vh);
                ldsm4t(bVlo + vrow + sw, vl);
                mma16816(o[2*ncp],   pa_hi, vh[0], vh[1]);
                mma16816(o[2*ncp+1], pa_hi, vh[2], vh[3]);
                mma16816(o[2*ncp],   pa_lo, vh[0], vh[1]);
                mma16816(o[2*ncp+1], pa_lo, vh[2], vh[3]);
                mma16816(o[2*ncp],   pa_hi, vl[0], vl[1]);
                mma16816(o[2*ncp+1], pa_hi, vl[2], vl[3]);
            }
        }
    }

    // ---- combine row sums across the 2 col-halves ----
    float* lr = (float*)(sm + O_LR);
    if ((lane & 3) == 0){
        lr[ch*64 + rb*16 + (lane>>2)]     = lsum0;
        lr[ch*64 + rb*16 + (lane>>2) + 8] = lsum1;
    }
    __syncthreads();
    const int r0 = rb*16 + (lane>>2);
    const float inv0 = 1.0f/(lr[r0]     + lr[64 + r0]);
    const float inv1 = 1.0f/(lr[r0 + 8] + lr[64 + r0 + 8]);

    // ---- write O (cols ch*128..) ----
    float* orow0 = Og + ((size_t)b*NSEQ + qbase + r0)*DH     + ch*128 + (lane&3)*2;
    float* orow1 = Og + ((size_t)b*NSEQ + qbase + r0 + 8)*DH + ch*128 + (lane&3)*2;
    #pragma unroll
    for (int nc=0; nc<16; ++nc){
        float2 w0; w0.x = o[nc][0]*inv0; w0.y = o[nc][1]*inv0;
        float2 w1; w1.x = o[nc][2]*inv1; w1.y = o[nc][3]*inv1;
        *(float2*)(orow0 + nc*8) = w0;
        *(float2*)(orow1 + nc*8) = w1;
    }
}

extern "C" void kernel_launch(void* const* d_in, const int* in_sizes, int n_in,
                              void* d_out, int out_size)
{
    const float* Q  = (const float*)d_in[0];
    const float* K  = (const float*)d_in[1];
    const float* V  = (const float*)d_in[2];
    const int*   PM = (const int*)d_in[3];
    float*       O  = (float*)d_out;

    cvt_kernel<<<NELEM/4/256, 256>>>(Q, K, V);

    cudaFuncSetAttribute(fa_fused_kernel,
                         cudaFuncAttributeMaxDynamicSharedMemorySize, SMEM_TOTAL);
    dim3 grid(NSEQ/BQ, BATCH);
    fa_fused_kernel<<<grid, 256, SMEM_TOTAL>>>(PM, O);
}